// round 1
// baseline (speedup 1.0000x reference)
#include <cuda_runtime.h>

#define NN 100000
#define EE 800000
#define NEG 0.2f

// ---------------- scratch (device globals; no allocation allowed) ----------------
__device__ __align__(16) float g_h [NN * 128];   // projected features (both layers)
__device__ __align__(16) float g_x2[NN * 128];   // layer-1 output / layer-2 input
__device__ __align__(16) float g_el[NN * 4];
__device__ __align__(16) float g_er[NN * 4];
__device__ __align__(16) float g_e [EE * 4];     // per-edge logits -> exp values (CSR order)
__device__ int g_deg [NN];
__device__ int g_off [NN];
__device__ int g_cur [NN];
__device__ int g_srcs[EE];                       // src node per CSR slot
__device__ int g_bsum[128];
__device__ int g_boff[128];

// ---------------- CSR build ----------------
__global__ void k_zero() {
    int i = blockIdx.x * blockDim.x + threadIdx.x;
    if (i < NN) g_deg[i] = 0;
}

__global__ void k_count(const int* __restrict__ dst) {
    int e = blockIdx.x * blockDim.x + threadIdx.x;
    if (e < EE) atomicAdd(&g_deg[dst[e]], 1);
}

__global__ void k_scanA() {
    __shared__ int sh[1024];
    int gid = blockIdx.x * 1024 + threadIdx.x;
    int v = (gid < NN) ? g_deg[gid] : 0;
    sh[threadIdx.x] = v;
    __syncthreads();
    for (int o = 1; o < 1024; o <<= 1) {
        int t = (threadIdx.x >= o) ? sh[threadIdx.x - o] : 0;
        __syncthreads();
        sh[threadIdx.x] += t;
        __syncthreads();
    }
    if (gid < NN) g_off[gid] = sh[threadIdx.x] - v;   // exclusive scan
    if (threadIdx.x == 1023) g_bsum[blockIdx.x] = sh[1023];
}

__global__ void k_scanB(int nb) {
    int run = 0;
    for (int i = 0; i < nb; i++) { g_boff[i] = run; run += g_bsum[i]; }
}

__global__ void k_scanC() {
    int i = blockIdx.x * blockDim.x + threadIdx.x;
    if (i < NN) {
        int v = g_off[i] + g_boff[i >> 10];
        g_off[i] = v;
        g_cur[i] = v;
    }
}

__global__ void k_fill(const int* __restrict__ src, const int* __restrict__ dst) {
    int e = blockIdx.x * blockDim.x + threadIdx.x;
    if (e < EE) {
        int p = atomicAdd(&g_cur[dst[e]], 1);
        g_srcs[p] = src[e];
    }
}
// after k_fill: g_off = start, g_cur = end of each node's CSR segment

// ---------------- GEMM + attention-logit epilogue ----------------
// Block = 256 threads (8 warps), each warp computes 4 nodes x 128 cols.
// Thread: 4 nodes x 4 cols register tile. W rows via LDG.128 (L1-resident, 64KB).
__global__ void k_gemm(const float* __restrict__ Xext, int useExt,
                       const float* __restrict__ W,
                       const float* __restrict__ al, const float* __restrict__ ar)
{
    __shared__ float4 xs[8][128];  // per-warp: 4 nodes' x packed per k
    const float* X = useExt ? Xext : g_x2;
    int w = threadIdx.x >> 5, lane = threadIdx.x & 31;
    int n0 = blockIdx.x * 32 + w * 4;

    float* xsf = (float*)&xs[w][0];
    #pragma unroll
    for (int r = 0; r < 4; r++) {
        int n = n0 + r;
        const float* xr = X + (long)n * 128;
        #pragma unroll
        for (int i = 0; i < 4; i++) {
            int c = lane + 32 * i;
            xsf[c * 4 + r] = (n < NN) ? xr[c] : 0.f;
        }
    }
    __syncwarp();

    float acc[4][4];
    #pragma unroll
    for (int r = 0; r < 4; r++)
        #pragma unroll
        for (int c = 0; c < 4; c++) acc[r][c] = 0.f;

    const float4* Wv = (const float4*)W;
    #pragma unroll 4
    for (int k = 0; k < 128; k++) {
        float4 wv = Wv[k * 32 + lane];
        float4 xk = xs[w][k];
        acc[0][0] += xk.x * wv.x; acc[0][1] += xk.x * wv.y; acc[0][2] += xk.x * wv.z; acc[0][3] += xk.x * wv.w;
        acc[1][0] += xk.y * wv.x; acc[1][1] += xk.y * wv.y; acc[1][2] += xk.y * wv.z; acc[1][3] += xk.y * wv.w;
        acc[2][0] += xk.z * wv.x; acc[2][1] += xk.z * wv.y; acc[2][2] += xk.z * wv.z; acc[2][3] += xk.z * wv.w;
        acc[3][0] += xk.w * wv.x; acc[3][1] += xk.w * wv.y; acc[3][2] += xk.w * wv.z; acc[3][3] += xk.w * wv.w;
    }

    // epilogue: store h, and el/er = per-head dot(h, attn) via 8-lane reductions.
    // lane covers cols f = 4*lane..4*lane+3, all within head = lane>>3;
    // attn flat index for col f is simply f.
    float4 al4 = ((const float4*)al)[lane];
    float4 ar4 = ((const float4*)ar)[lane];
    int head = lane >> 3;
    #pragma unroll
    for (int r = 0; r < 4; r++) {
        int n = n0 + r;
        float pel = acc[r][0]*al4.x + acc[r][1]*al4.y + acc[r][2]*al4.z + acc[r][3]*al4.w;
        float per = acc[r][0]*ar4.x + acc[r][1]*ar4.y + acc[r][2]*ar4.z + acc[r][3]*ar4.w;
        #pragma unroll
        for (int o = 1; o < 8; o <<= 1) {
            pel += __shfl_xor_sync(0xffffffffu, pel, o);
            per += __shfl_xor_sync(0xffffffffu, per, o);
        }
        if (n < NN) {
            ((float4*)g_h)[n * 32 + lane] = make_float4(acc[r][0], acc[r][1], acc[r][2], acc[r][3]);
            if ((lane & 7) == 0) {
                g_el[n * 4 + head] = pel;
                g_er[n * 4 + head] = per;
            }
        }
    }
}

// ---------------- per-dst-node softmax + aggregation (1 warp / node) ----------------
__global__ void k_agg(const float* __restrict__ bias, float* __restrict__ outExt, int layer2)
{
    int d    = (blockIdx.x * blockDim.x + threadIdx.x) >> 5;  // grid sized exactly: d < NN
    int lane = threadIdx.x & 31;
    int p0 = g_off[d], p1 = g_cur[d];

    float4 er4 = ((const float4*)g_er)[d];

    // phase A: edge logits + running max (lane-parallel over edges)
    float m0 = -3e38f, m1 = -3e38f, m2 = -3e38f, m3 = -3e38f;
    for (int p = p0 + lane; p < p1; p += 32) {
        int s = g_srcs[p];
        float4 el4 = ((const float4*)g_el)[s];
        float e0 = el4.x + er4.x; e0 = (e0 > 0.f) ? e0 : NEG * e0;
        float e1 = el4.y + er4.y; e1 = (e1 > 0.f) ? e1 : NEG * e1;
        float e2 = el4.z + er4.z; e2 = (e2 > 0.f) ? e2 : NEG * e2;
        float e3 = el4.w + er4.w; e3 = (e3 > 0.f) ? e3 : NEG * e3;
        ((float4*)g_e)[p] = make_float4(e0, e1, e2, e3);
        m0 = fmaxf(m0, e0); m1 = fmaxf(m1, e1); m2 = fmaxf(m2, e2); m3 = fmaxf(m3, e3);
    }
    #pragma unroll
    for (int o = 16; o > 0; o >>= 1) {
        m0 = fmaxf(m0, __shfl_xor_sync(0xffffffffu, m0, o));
        m1 = fmaxf(m1, __shfl_xor_sync(0xffffffffu, m1, o));
        m2 = fmaxf(m2, __shfl_xor_sync(0xffffffffu, m2, o));
        m3 = fmaxf(m3, __shfl_xor_sync(0xffffffffu, m3, o));
    }

    // phase B: exp + sum (stores exp back)
    float s0 = 0.f, s1 = 0.f, s2 = 0.f, s3 = 0.f;
    for (int p = p0 + lane; p < p1; p += 32) {
        float4 e = ((float4*)g_e)[p];
        float x0 = __expf(e.x - m0), x1 = __expf(e.y - m1);
        float x2 = __expf(e.z - m2), x3 = __expf(e.w - m3);
        ((float4*)g_e)[p] = make_float4(x0, x1, x2, x3);
        s0 += x0; s1 += x1; s2 += x2; s3 += x3;
    }
    #pragma unroll
    for (int o = 16; o > 0; o >>= 1) {
        s0 += __shfl_xor_sync(0xffffffffu, s0, o);
        s1 += __shfl_xor_sync(0xffffffffu, s1, o);
        s2 += __shfl_xor_sync(0xffffffffu, s2, o);
        s3 += __shfl_xor_sync(0xffffffffu, s3, o);
    }
    int hq = lane >> 3;
    float sv  = (hq == 0) ? s0 : (hq == 1) ? s1 : (hq == 2) ? s2 : s3;
    float inv = (sv > 0.f) ? (1.f / sv) : 0.f;

    __syncwarp();  // phase-B cross-lane exp values must be visible

    // phase C: accumulate a * h[src] (whole warp per edge; coalesced 512B gathers)
    float a0 = 0.f, a1 = 0.f, a2 = 0.f, a3 = 0.f;
    #pragma unroll 2
    for (int p = p0; p < p1; p++) {
        int s = g_srcs[p];                 // broadcast
        float ex = g_e[p * 4 + hq];        // 4 distinct addrs per warp
        float av = ex * inv;
        float4 hv = ((const float4*)g_h)[s * 32 + lane];
        a0 += av * hv.x; a1 += av * hv.y; a2 += av * hv.z; a3 += av * hv.w;
    }

    if (!layer2) {
        float4 b = ((const float4*)bias)[lane];
        a0 = fmaxf(a0 + b.x, 0.f); a1 = fmaxf(a1 + b.y, 0.f);
        a2 = fmaxf(a2 + b.z, 0.f); a3 = fmaxf(a3 + b.w, 0.f);
        ((float4*)g_x2)[d * 32 + lane] = make_float4(a0, a1, a2, a3);
    } else {
        float4 b = ((const float4*)bias)[lane];
        a0 += b.x; a1 += b.y; a2 += b.z; a3 += b.w;
        // mean over heads: sum lanes {l, l+8, l+16, l+24} (same out index, 4 heads)
        a0 += __shfl_xor_sync(0xffffffffu, a0, 8);  a0 += __shfl_xor_sync(0xffffffffu, a0, 16);
        a1 += __shfl_xor_sync(0xffffffffu, a1, 8);  a1 += __shfl_xor_sync(0xffffffffu, a1, 16);
        a2 += __shfl_xor_sync(0xffffffffu, a2, 8);  a2 += __shfl_xor_sync(0xffffffffu, a2, 16);
        a3 += __shfl_xor_sync(0xffffffffu, a3, 8);  a3 += __shfl_xor_sync(0xffffffffu, a3, 16);
        if (lane < 8)
            ((float4*)outExt)[d * 8 + lane] =
                make_float4(0.25f * a0, 0.25f * a1, 0.25f * a2, 0.25f * a3);
    }
}

// ---------------- launch ----------------
extern "C" void kernel_launch(void* const* d_in, const int* in_sizes, int n_in,
                              void* d_out, int out_size)
{
    const float* feat = (const float*)d_in[0];
    const int*   src  = (const int*)  d_in[1];
    const int*   dst  = (const int*)  d_in[2];
    const float* W1   = (const float*)d_in[3];
    const float* al1  = (const float*)d_in[4];
    const float* ar1  = (const float*)d_in[5];
    const float* b1   = (const float*)d_in[6];
    const float* W2   = (const float*)d_in[7];
    const float* al2  = (const float*)d_in[8];
    const float* ar2  = (const float*)d_in[9];
    const float* b2   = (const float*)d_in[10];
    float* out = (float*)d_out;

    // CSR build (graph shared by both layers)
    k_zero <<<(NN + 255) / 256, 256>>>();
    k_count<<<(EE + 255) / 256, 256>>>(dst);
    int nb = (NN + 1023) / 1024;
    k_scanA<<<nb, 1024>>>();
    k_scanB<<<1, 1>>>(nb);
    k_scanC<<<(NN + 255) / 256, 256>>>();
    k_fill <<<(EE + 255) / 256, 256>>>(src, dst);

    // layer 1
    k_gemm<<<(NN + 31) / 32, 256>>>(feat, 1, W1, al1, ar1);
    k_agg <<<NN / 4, 128>>>(b1, nullptr, 0);

    // layer 2
    k_gemm<<<(NN + 31) / 32, 256>>>(nullptr, 0, W2, al2, ar2);
    k_agg <<<NN / 4, 128>>>(b2, out, 1);
}

// round 2
// speedup vs baseline: 1.1294x; 1.1294x over previous
#include <cuda_runtime.h>

#define NN 100000
#define EE 800000
#define NEG 0.2f

// ---------------- scratch (device globals; no allocation allowed) ----------------
__device__ __align__(16) float g_h [NN * 128];   // projected features (both layers)
__device__ __align__(16) float g_x2[NN * 128];   // layer-1 output / layer-2 input
__device__ __align__(16) float g_el[NN * 4];
__device__ __align__(16) float g_er[NN * 4];
__device__ __align__(16) float g_e [EE * 4];     // per-edge exp values (CSR order)
__device__ int g_deg [NN];
__device__ int g_off [NN];
__device__ int g_cur [NN];
__device__ int g_srcs[EE];                       // src node per CSR slot
__device__ int g_tot;

// packed f32x2 FMA: 2 FMAs per issue slot (FFMA2) — PTX-only path
__device__ __forceinline__ void ffma2(float2& d, float2 a, float2 b) {
    asm("fma.rn.f32x2 %0, %1, %2, %0;"
        : "+l"(reinterpret_cast<unsigned long long&>(d))
        : "l"(reinterpret_cast<const unsigned long long&>(a)),
          "l"(reinterpret_cast<const unsigned long long&>(b)));
}
__device__ __forceinline__ float2 dup(float x) { return make_float2(x, x); }

// ---------------- CSR build (scan-free) ----------------
__global__ void k_zero() {
    int i = blockIdx.x * blockDim.x + threadIdx.x;
    if (i < NN) g_deg[i] = 0;
    if (i == 0) g_tot = 0;
}

__global__ void k_count(const int* __restrict__ dst) {
    int e = blockIdx.x * blockDim.x + threadIdx.x;
    if (e < EE) atomicAdd(&g_deg[dst[e]], 1);
}

// warp-level exclusive scan + one global atomic per warp; segment ORDER in the
// CSR is arbitrary (only per-dst grouping matters), so no global scan needed.
__global__ void k_off() {
    int i = blockIdx.x * blockDim.x + threadIdx.x;
    int lane = threadIdx.x & 31;
    int v = (i < NN) ? g_deg[i] : 0;
    int x = v;
    #pragma unroll
    for (int o = 1; o < 32; o <<= 1) {
        int t = __shfl_up_sync(0xffffffffu, x, o);
        if (lane >= o) x += t;
    }
    int excl = x - v;
    int wsum = __shfl_sync(0xffffffffu, x, 31);
    int base = 0;
    if (lane == 31) base = atomicAdd(&g_tot, wsum);
    base = __shfl_sync(0xffffffffu, base, 31);
    if (i < NN) {
        g_off[i] = base + excl;
        g_cur[i] = base + excl;
    }
}

__global__ void k_fill(const int* __restrict__ src, const int* __restrict__ dst) {
    int e = blockIdx.x * blockDim.x + threadIdx.x;
    if (e < EE) {
        int p = atomicAdd(&g_cur[dst[e]], 1);
        g_srcs[p] = src[e];
    }
}
// after k_fill: g_off = start, g_cur = end of each node's CSR segment

// ---------------- GEMM + attention-logit epilogue (FFMA2 core) ----------------
// Block = 256 threads (8 warps), each warp computes 4 nodes x 128 cols.
// Thread register tile: 4 nodes x 4 cols as 8 packed float2 accumulators.
__global__ void k_gemm(const float* __restrict__ Xext, int useExt,
                       const float* __restrict__ W,
                       const float* __restrict__ al, const float* __restrict__ ar)
{
    __shared__ float4 xs[8][128];  // per-warp: 4 nodes' x packed per k
    const float* X = useExt ? Xext : g_x2;
    int w = threadIdx.x >> 5, lane = threadIdx.x & 31;
    int n0 = blockIdx.x * 32 + w * 4;

    float* xsf = (float*)&xs[w][0];
    #pragma unroll
    for (int r = 0; r < 4; r++) {
        int n = n0 + r;
        const float* xr = X + (long)n * 128;
        #pragma unroll
        for (int i = 0; i < 4; i++) {
            int c = lane + 32 * i;
            xsf[c * 4 + r] = (n < NN) ? xr[c] : 0.f;
        }
    }
    __syncwarp();

    float2 acc[4][2];  // [col][rowpair] : .x = row 2j, .y = row 2j+1
    #pragma unroll
    for (int c = 0; c < 4; c++) {
        acc[c][0] = make_float2(0.f, 0.f);
        acc[c][1] = make_float2(0.f, 0.f);
    }

    const float4* Wv = (const float4*)W;
    #pragma unroll 4
    for (int k = 0; k < 128; k++) {
        float4 wv = Wv[k * 32 + lane];
        float4 xk = xs[w][k];
        float2 x01 = make_float2(xk.x, xk.y);
        float2 x23 = make_float2(xk.z, xk.w);
        float2 w0 = dup(wv.x), w1 = dup(wv.y), w2 = dup(wv.z), w3 = dup(wv.w);
        ffma2(acc[0][0], x01, w0); ffma2(acc[0][1], x23, w0);
        ffma2(acc[1][0], x01, w1); ffma2(acc[1][1], x23, w1);
        ffma2(acc[2][0], x01, w2); ffma2(acc[2][1], x23, w2);
        ffma2(acc[3][0], x01, w3); ffma2(acc[3][1], x23, w3);
    }

    // unpack to [row][col]
    float av[4][4];
    #pragma unroll
    for (int c = 0; c < 4; c++) {
        av[0][c] = acc[c][0].x; av[1][c] = acc[c][0].y;
        av[2][c] = acc[c][1].x; av[3][c] = acc[c][1].y;
    }

    // epilogue: store h, and el/er = per-head dot(h, attn) via 8-lane reductions.
    float4 al4 = ((const float4*)al)[lane];
    float4 ar4 = ((const float4*)ar)[lane];
    int head = lane >> 3;
    #pragma unroll
    for (int r = 0; r < 4; r++) {
        int n = n0 + r;
        float pel = av[r][0]*al4.x + av[r][1]*al4.y + av[r][2]*al4.z + av[r][3]*al4.w;
        float per = av[r][0]*ar4.x + av[r][1]*ar4.y + av[r][2]*ar4.z + av[r][3]*ar4.w;
        #pragma unroll
        for (int o = 1; o < 8; o <<= 1) {
            pel += __shfl_xor_sync(0xffffffffu, pel, o);
            per += __shfl_xor_sync(0xffffffffu, per, o);
        }
        if (n < NN) {
            ((float4*)g_h)[n * 32 + lane] = make_float4(av[r][0], av[r][1], av[r][2], av[r][3]);
            if ((lane & 7) == 0) {
                g_el[n * 4 + head] = pel;
                g_er[n * 4 + head] = per;
            }
        }
    }
}

// ---------------- per-dst-node softmax + aggregation (1 warp / node) ----------------
// No max-subtraction: logits are O(1)-scale here (fminf(.,80) guards overflow and
// is a mathematical no-op when never hit; softmax ratio is identical either way).
__global__ void k_agg(const float* __restrict__ bias, float* __restrict__ outExt, int layer2)
{
    int d    = (blockIdx.x * blockDim.x + threadIdx.x) >> 5;  // grid sized exactly: d < NN
    int lane = threadIdx.x & 31;
    int p0 = g_off[d], p1 = g_cur[d];

    float4 er4 = ((const float4*)g_er)[d];

    // phase AB: logits -> exp -> store + sum (single pass)
    float s0 = 0.f, s1 = 0.f, s2 = 0.f, s3 = 0.f;
    for (int p = p0 + lane; p < p1; p += 32) {
        int s = g_srcs[p];
        float4 el4 = ((const float4*)g_el)[s];
        float e0 = el4.x + er4.x; e0 = (e0 > 0.f) ? e0 : NEG * e0;
        float e1 = el4.y + er4.y; e1 = (e1 > 0.f) ? e1 : NEG * e1;
        float e2 = el4.z + er4.z; e2 = (e2 > 0.f) ? e2 : NEG * e2;
        float e3 = el4.w + er4.w; e3 = (e3 > 0.f) ? e3 : NEG * e3;
        float x0 = __expf(fminf(e0, 80.f)), x1 = __expf(fminf(e1, 80.f));
        float x2 = __expf(fminf(e2, 80.f)), x3 = __expf(fminf(e3, 80.f));
        ((float4*)g_e)[p] = make_float4(x0, x1, x2, x3);
        s0 += x0; s1 += x1; s2 += x2; s3 += x3;
    }
    #pragma unroll
    for (int o = 16; o > 0; o >>= 1) {
        s0 += __shfl_xor_sync(0xffffffffu, s0, o);
        s1 += __shfl_xor_sync(0xffffffffu, s1, o);
        s2 += __shfl_xor_sync(0xffffffffu, s2, o);
        s3 += __shfl_xor_sync(0xffffffffu, s3, o);
    }
    int hq = lane >> 3;
    float sv  = (hq == 0) ? s0 : (hq == 1) ? s1 : (hq == 2) ? s2 : s3;
    float inv = (sv > 0.f) ? (1.f / sv) : 0.f;

    __syncwarp();  // cross-lane exp values must be visible before phase C reads

    // phase C: accumulate ex * h[src]; 2-edge pipeline for MLP, inv applied at end.
    float2 A0 = make_float2(0.f, 0.f), A1 = A0, B0 = A0, B1 = A0;
    int p = p0;
    for (; p + 2 <= p1; p += 2) {
        int sA = g_srcs[p], sB = g_srcs[p + 1];
        float eA = g_e[p * 4 + hq];
        float eB = g_e[(p + 1) * 4 + hq];
        float4 hA = ((const float4*)g_h)[sA * 32 + lane];
        float4 hB = ((const float4*)g_h)[sB * 32 + lane];
        float2 dA = dup(eA), dB = dup(eB);
        ffma2(A0, make_float2(hA.x, hA.y), dA);
        ffma2(A1, make_float2(hA.z, hA.w), dA);
        ffma2(B0, make_float2(hB.x, hB.y), dB);
        ffma2(B1, make_float2(hB.z, hB.w), dB);
    }
    if (p < p1) {
        int sA = g_srcs[p];
        float eA = g_e[p * 4 + hq];
        float4 hA = ((const float4*)g_h)[sA * 32 + lane];
        float2 dA = dup(eA);
        ffma2(A0, make_float2(hA.x, hA.y), dA);
        ffma2(A1, make_float2(hA.z, hA.w), dA);
    }
    float a0 = (A0.x + B0.x) * inv;
    float a1 = (A0.y + B0.y) * inv;
    float a2 = (A1.x + B1.x) * inv;
    float a3 = (A1.y + B1.y) * inv;

    if (!layer2) {
        float4 b = ((const float4*)bias)[lane];
        a0 = fmaxf(a0 + b.x, 0.f); a1 = fmaxf(a1 + b.y, 0.f);
        a2 = fmaxf(a2 + b.z, 0.f); a3 = fmaxf(a3 + b.w, 0.f);
        ((float4*)g_x2)[d * 32 + lane] = make_float4(a0, a1, a2, a3);
    } else {
        float4 b = ((const float4*)bias)[lane];
        a0 += b.x; a1 += b.y; a2 += b.z; a3 += b.w;
        // mean over heads: sum lanes {l, l+8, l+16, l+24} (same out index, 4 heads)
        a0 += __shfl_xor_sync(0xffffffffu, a0, 8);  a0 += __shfl_xor_sync(0xffffffffu, a0, 16);
        a1 += __shfl_xor_sync(0xffffffffu, a1, 8);  a1 += __shfl_xor_sync(0xffffffffu, a1, 16);
        a2 += __shfl_xor_sync(0xffffffffu, a2, 8);  a2 += __shfl_xor_sync(0xffffffffu, a2, 16);
        a3 += __shfl_xor_sync(0xffffffffu, a3, 8);  a3 += __shfl_xor_sync(0xffffffffu, a3, 16);
        if (lane < 8)
            ((float4*)outExt)[d * 8 + lane] =
                make_float4(0.25f * a0, 0.25f * a1, 0.25f * a2, 0.25f * a3);
    }
}

// ---------------- launch ----------------
extern "C" void kernel_launch(void* const* d_in, const int* in_sizes, int n_in,
                              void* d_out, int out_size)
{
    const float* feat = (const float*)d_in[0];
    const int*   src  = (const int*)  d_in[1];
    const int*   dst  = (const int*)  d_in[2];
    const float* W1   = (const float*)d_in[3];
    const float* al1  = (const float*)d_in[4];
    const float* ar1  = (const float*)d_in[5];
    const float* b1   = (const float*)d_in[6];
    const float* W2   = (const float*)d_in[7];
    const float* al2  = (const float*)d_in[8];
    const float* ar2  = (const float*)d_in[9];
    const float* b2   = (const float*)d_in[10];
    float* out = (float*)d_out;

    // CSR build (graph shared by both layers)
    k_zero <<<(NN + 255) / 256, 256>>>();
    k_count<<<(EE + 255) / 256, 256>>>(dst);
    k_off  <<<(NN + 255) / 256, 256>>>();
    k_fill <<<(EE + 255) / 256, 256>>>(src, dst);

    // layer 1
    k_gemm<<<(NN + 31) / 32, 256>>>(feat, 1, W1, al1, ar1);
    k_agg <<<NN / 4, 128>>>(b1, nullptr, 0);

    // layer 2
    k_gemm<<<(NN + 31) / 32, 256>>>(nullptr, 0, W2, al2, ar2);
    k_agg <<<NN / 4, 128>>>(b2, out, 1);
}

// round 3
// speedup vs baseline: 1.2518x; 1.1084x over previous
#include <cuda_runtime.h>

#define NN 100000
#define EE 800000
#define NEG 0.2f

// ---------------- scratch (device globals; no allocation allowed) ----------------
__device__ __align__(16) float g_h [NN * 128];   // projected features (both layers)
__device__ __align__(16) float g_x2[NN * 128];   // layer-1 output / layer-2 input
__device__ __align__(16) float g_el[NN * 4];
__device__ __align__(16) float g_er[NN * 4];
__device__ int g_deg [NN];
__device__ int g_off [NN];
__device__ int g_cur [NN];
__device__ int g_srcs[EE];                       // src node per CSR slot
__device__ int g_tot;

// packed f32x2 FMA: 2 FMAs per issue slot (FFMA2) — PTX-only path
__device__ __forceinline__ void ffma2(float2& d, float2 a, float2 b) {
    asm("fma.rn.f32x2 %0, %1, %2, %0;"
        : "+l"(reinterpret_cast<unsigned long long&>(d))
        : "l"(reinterpret_cast<const unsigned long long&>(a)),
          "l"(reinterpret_cast<const unsigned long long&>(b)));
}
__device__ __forceinline__ float2 dup(float x) { return make_float2(x, x); }

// ---------------- CSR build (scan-free) ----------------
__global__ void k_zero() {
    int i = blockIdx.x * blockDim.x + threadIdx.x;
    if (i < NN) g_deg[i] = 0;
    if (i == 0) g_tot = 0;
}

__global__ void k_count(const int* __restrict__ dst) {
    int e = blockIdx.x * blockDim.x + threadIdx.x;
    if (e < EE) atomicAdd(&g_deg[dst[e]], 1);
}

// warp-level exclusive scan + one global atomic per warp; CSR segment ORDER is
// arbitrary (only per-dst grouping matters), so no global scan needed.
__global__ void k_off() {
    int i = blockIdx.x * blockDim.x + threadIdx.x;
    int lane = threadIdx.x & 31;
    int v = (i < NN) ? g_deg[i] : 0;
    int x = v;
    #pragma unroll
    for (int o = 1; o < 32; o <<= 1) {
        int t = __shfl_up_sync(0xffffffffu, x, o);
        if (lane >= o) x += t;
    }
    int excl = x - v;
    int wsum = __shfl_sync(0xffffffffu, x, 31);
    int base = 0;
    if (lane == 31) base = atomicAdd(&g_tot, wsum);
    base = __shfl_sync(0xffffffffu, base, 31);
    if (i < NN) {
        g_off[i] = base + excl;
        g_cur[i] = base + excl;
    }
}

__global__ void k_fill(const int* __restrict__ src, const int* __restrict__ dst) {
    int e = blockIdx.x * blockDim.x + threadIdx.x;
    if (e < EE) {
        int p = atomicAdd(&g_cur[dst[e]], 1);
        g_srcs[p] = src[e];
    }
}
// after k_fill: g_off = start, g_cur = end of each node's CSR segment

// ---------------- GEMM + attention-logit epilogue (FFMA2 core) ----------------
// Block = 256 threads (8 warps), each warp computes 4 nodes x 128 cols.
// At the fp32 FMA roofline (~49us per GEMM).
__global__ void k_gemm(const float* __restrict__ Xext, int useExt,
                       const float* __restrict__ W,
                       const float* __restrict__ al, const float* __restrict__ ar)
{
    __shared__ float4 xs[8][128];  // per-warp: 4 nodes' x packed per k
    const float* X = useExt ? Xext : g_x2;
    int w = threadIdx.x >> 5, lane = threadIdx.x & 31;
    int n0 = blockIdx.x * 32 + w * 4;

    float* xsf = (float*)&xs[w][0];
    #pragma unroll
    for (int r = 0; r < 4; r++) {
        int n = n0 + r;
        const float* xr = X + (long)n * 128;
        #pragma unroll
        for (int i = 0; i < 4; i++) {
            int c = lane + 32 * i;
            xsf[c * 4 + r] = (n < NN) ? xr[c] : 0.f;
        }
    }
    __syncwarp();

    float2 acc[4][2];  // [col][rowpair]
    #pragma unroll
    for (int c = 0; c < 4; c++) {
        acc[c][0] = make_float2(0.f, 0.f);
        acc[c][1] = make_float2(0.f, 0.f);
    }

    const float4* Wv = (const float4*)W;
    #pragma unroll 4
    for (int k = 0; k < 128; k++) {
        float4 wv = Wv[k * 32 + lane];
        float4 xk = xs[w][k];
        float2 x01 = make_float2(xk.x, xk.y);
        float2 x23 = make_float2(xk.z, xk.w);
        float2 w0 = dup(wv.x), w1 = dup(wv.y), w2 = dup(wv.z), w3 = dup(wv.w);
        ffma2(acc[0][0], x01, w0); ffma2(acc[0][1], x23, w0);
        ffma2(acc[1][0], x01, w1); ffma2(acc[1][1], x23, w1);
        ffma2(acc[2][0], x01, w2); ffma2(acc[2][1], x23, w2);
        ffma2(acc[3][0], x01, w3); ffma2(acc[3][1], x23, w3);
    }

    float av[4][4];
    #pragma unroll
    for (int c = 0; c < 4; c++) {
        av[0][c] = acc[c][0].x; av[1][c] = acc[c][0].y;
        av[2][c] = acc[c][1].x; av[3][c] = acc[c][1].y;
    }

    // epilogue: store h, and el/er = per-head dot(h, attn) via 8-lane reductions.
    float4 al4 = ((const float4*)al)[lane];
    float4 ar4 = ((const float4*)ar)[lane];
    int head = lane >> 3;
    #pragma unroll
    for (int r = 0; r < 4; r++) {
        int n = n0 + r;
        float pel = av[r][0]*al4.x + av[r][1]*al4.y + av[r][2]*al4.z + av[r][3]*al4.w;
        float per = av[r][0]*ar4.x + av[r][1]*ar4.y + av[r][2]*ar4.z + av[r][3]*ar4.w;
        #pragma unroll
        for (int o = 1; o < 8; o <<= 1) {
            pel += __shfl_xor_sync(0xffffffffu, pel, o);
            per += __shfl_xor_sync(0xffffffffu, per, o);
        }
        if (n < NN) {
            ((float4*)g_h)[n * 32 + lane] = make_float4(av[r][0], av[r][1], av[r][2], av[r][3]);
            if ((lane & 7) == 0) {
                g_el[n * 4 + head] = pel;
                g_er[n * 4 + head] = per;
            }
        }
    }
}

// ---------------- fused softmax + aggregation, SINGLE edge pass ----------------
// out = (sum_e ex_e * h[src_e]) / (sum_e ex_e): normalization deferred, so one
// pass suffices. One warp per dst node; whole warp per edge (coalesced 512B h
// gather). Each lane computes its own head's exp (8x redundant; MUFU is cheap).
// Every lane sees every edge, so each lane holds the full per-head exp-sum —
// no cross-lane reductions needed. No max-subtraction: logits are O(1)-scale;
// fminf(.,80) guards overflow and is a no-op otherwise (softmax is shift-inv).
__global__ void k_agg(const float* __restrict__ bias, float* __restrict__ outExt, int layer2)
{
    int d    = (blockIdx.x * blockDim.x + threadIdx.x) >> 5;
    int lane = threadIdx.x & 31;
    if (d >= NN) return;
    int hq = lane >> 3;
    int p0 = g_off[d], p1 = g_cur[d];

    float er_h = g_er[d * 4 + hq];

    float sA = 0.f, sB = 0.f;
    float2 A0 = make_float2(0.f, 0.f), A1 = A0, B0 = A0, B1 = A0;

    int p = p0;
    for (; p + 2 <= p1; p += 2) {
        int nA = g_srcs[p];                      // broadcast
        int nB = g_srcs[p + 1];
        float eA = g_el[nA * 4 + hq] + er_h;     // 1 sector per warp
        float eB = g_el[nB * 4 + hq] + er_h;
        float4 hA = ((const float4*)g_h)[nA * 32 + lane];
        float4 hB = ((const float4*)g_h)[nB * 32 + lane];
        eA = (eA > 0.f) ? eA : NEG * eA;
        eB = (eB > 0.f) ? eB : NEG * eB;
        float xA = __expf(fminf(eA, 80.f));
        float xB = __expf(fminf(eB, 80.f));
        sA += xA; sB += xB;
        float2 dA = dup(xA), dB = dup(xB);
        ffma2(A0, make_float2(hA.x, hA.y), dA);
        ffma2(A1, make_float2(hA.z, hA.w), dA);
        ffma2(B0, make_float2(hB.x, hB.y), dB);
        ffma2(B1, make_float2(hB.z, hB.w), dB);
    }
    if (p < p1) {
        int nA = g_srcs[p];
        float eA = g_el[nA * 4 + hq] + er_h;
        float4 hA = ((const float4*)g_h)[nA * 32 + lane];
        eA = (eA > 0.f) ? eA : NEG * eA;
        float xA = __expf(fminf(eA, 80.f));
        sA += xA;
        float2 dA = dup(xA);
        ffma2(A0, make_float2(hA.x, hA.y), dA);
        ffma2(A1, make_float2(hA.z, hA.w), dA);
    }

    float s = sA + sB;
    float inv = (s > 0.f) ? (1.f / s) : 0.f;
    float a0 = (A0.x + B0.x) * inv;
    float a1 = (A0.y + B0.y) * inv;
    float a2 = (A1.x + B1.x) * inv;
    float a3 = (A1.y + B1.y) * inv;

    if (!layer2) {
        float4 b = ((const float4*)bias)[lane];
        a0 = fmaxf(a0 + b.x, 0.f); a1 = fmaxf(a1 + b.y, 0.f);
        a2 = fmaxf(a2 + b.z, 0.f); a3 = fmaxf(a3 + b.w, 0.f);
        ((float4*)g_x2)[d * 32 + lane] = make_float4(a0, a1, a2, a3);
    } else {
        float4 b = ((const float4*)bias)[lane];
        a0 += b.x; a1 += b.y; a2 += b.z; a3 += b.w;
        // mean over heads: lanes {l, l+8, l+16, l+24} hold the 4 heads of out idx
        a0 += __shfl_xor_sync(0xffffffffu, a0, 8);  a0 += __shfl_xor_sync(0xffffffffu, a0, 16);
        a1 += __shfl_xor_sync(0xffffffffu, a1, 8);  a1 += __shfl_xor_sync(0xffffffffu, a1, 16);
        a2 += __shfl_xor_sync(0xffffffffu, a2, 8);  a2 += __shfl_xor_sync(0xffffffffu, a2, 16);
        a3 += __shfl_xor_sync(0xffffffffu, a3, 8);  a3 += __shfl_xor_sync(0xffffffffu, a3, 16);
        if (lane < 8)
            ((float4*)outExt)[d * 8 + lane] =
                make_float4(0.25f * a0, 0.25f * a1, 0.25f * a2, 0.25f * a3);
    }
}

// ---------------- launch ----------------
extern "C" void kernel_launch(void* const* d_in, const int* in_sizes, int n_in,
                              void* d_out, int out_size)
{
    const float* feat = (const float*)d_in[0];
    const int*   src  = (const int*)  d_in[1];
    const int*   dst  = (const int*)  d_in[2];
    const float* W1   = (const float*)d_in[3];
    const float* al1  = (const float*)d_in[4];
    const float* ar1  = (const float*)d_in[5];
    const float* b1   = (const float*)d_in[6];
    const float* W2   = (const float*)d_in[7];
    const float* al2  = (const float*)d_in[8];
    const float* ar2  = (const float*)d_in[9];
    const float* b2   = (const float*)d_in[10];
    float* out = (float*)d_out;

    // CSR build (graph shared by both layers)
    k_zero <<<(NN + 255) / 256, 256>>>();
    k_count<<<(EE + 255) / 256, 256>>>(dst);
    k_off  <<<(NN + 255) / 256, 256>>>();
    k_fill <<<(EE + 255) / 256, 256>>>(src, dst);

    // layer 1
    k_gemm<<<(NN + 31) / 32, 256>>>(feat, 1, W1, al1, ar1);
    k_agg <<<(NN * 32 + 255) / 256, 256>>>(b1, nullptr, 0);

    // layer 2
    k_gemm<<<(NN + 31) / 32, 256>>>(nullptr, 0, W2, al2, ar2);
    k_agg <<<(NN * 32 + 255) / 256, 256>>>(b2, out, 1);
}